// round 1
// baseline (speedup 1.0000x reference)
#include <cuda_runtime.h>

// OuterProductMean (AlphaFold Evoformer style), fp32 baseline, fused epilogue.
//
// Pipeline:
//   K1: per-(s,i) LayerNorm over c_m=256 + dual projection -> a_g[s][i*32+c], b_g[s][i*32+c]
//   K2: transpose wo[128][1024] -> woT[1024][128]  (coalesced z-reads in K3)
//   K3 (fused): per CTA: 128x128x128 GEMM o-tile (16 (i,j) pairs) in registers,
//               stage to SMEM, contract vs woT -> 16x128 outputs, scale by 1/128.

#define S_DIM 128
#define R_DIM 256
#define CM    256
#define CC    32
#define CZ    128
#define MDIM  (R_DIM * CC)     // 8192

// SMEM staging strides for the o tile (pad to kill store-bank conflicts,
// keep 16B alignment for float4 reads: col stride 36 (mod4=0, mod32=4),
// pair stride 32*36+4 = 1156 (mod4=0, mod32=4)).
#define OS_CSTRIDE 36
#define OS_PSTRIDE (32 * OS_CSTRIDE + 4)   // 1156
#define SMEM_BYTES (2 * 128 * 128 * 4)     // 131072 (As+Bs; Os 73984B reuses it)

__device__ float g_a[S_DIM * MDIM];          // a[s][i*32+c], m-contiguous
__device__ float g_b[S_DIM * MDIM];          // b[s][j*32+d]
__device__ float g_woT[CC * CC * CZ];        // woT[k=c*32+d][z]

// ---------------------------------------------------------------------------
// K1: LayerNorm + projections. One block per (s,i) row, 256 threads.
// ---------------------------------------------------------------------------
__global__ void ln_proj_kernel(const float* __restrict__ m,
                               const float* __restrict__ ln_w,
                               const float* __restrict__ ln_b,
                               const float* __restrict__ w1,
                               const float* __restrict__ b1,
                               const float* __restrict__ w2,
                               const float* __restrict__ b2) {
    const int i = blockIdx.x;   // residue
    const int s = blockIdx.y;   // sequence
    const int tid = threadIdx.x;

    __shared__ float xs[CM];
    __shared__ float red[CM];
    __shared__ float stats[2];

    const float* row = m + ((size_t)s * R_DIM + i) * CM;
    const float x = row[tid];

    // mean
    red[tid] = x;
    __syncthreads();
    #pragma unroll
    for (int off = 128; off > 0; off >>= 1) {
        if (tid < off) red[tid] += red[tid + off];
        __syncthreads();
    }
    if (tid == 0) stats[0] = red[0] * (1.0f / CM);
    __syncthreads();
    const float mu = stats[0];
    const float dx = x - mu;

    // variance
    red[tid] = dx * dx;
    __syncthreads();
    #pragma unroll
    for (int off = 128; off > 0; off >>= 1) {
        if (tid < off) red[tid] += red[tid + off];
        __syncthreads();
    }
    if (tid == 0) stats[1] = rsqrtf(red[0] * (1.0f / CM) + 1e-5f);
    __syncthreads();

    xs[tid] = dx * stats[1] * ln_w[tid] + ln_b[tid];
    __syncthreads();

    // 64 dot products of length 256: one warp per output, 8 at a time.
    const int w = tid >> 5, lane = tid & 31;
    for (int cc = w; cc < 2 * CC; cc += 8) {
        const float* wr = (cc < CC) ? (w1 + (size_t)cc * CM)
                                    : (w2 + (size_t)(cc - CC) * CM);
        float p = 0.f;
        #pragma unroll
        for (int k = lane; k < CM; k += 32) p += xs[k] * wr[k];
        #pragma unroll
        for (int o = 16; o > 0; o >>= 1) p += __shfl_xor_sync(0xffffffffu, p, o);
        if (lane == 0) {
            if (cc < CC)
                g_a[(size_t)s * MDIM + i * CC + cc] = p + b1[cc];
            else
                g_b[(size_t)s * MDIM + i * CC + (cc - CC)] = p + b2[cc - CC];
        }
    }
}

// ---------------------------------------------------------------------------
// K2: woT[k][z] = wo[z][k]
// ---------------------------------------------------------------------------
__global__ void transpose_wo_kernel(const float* __restrict__ wo) {
    const int idx = blockIdx.x * blockDim.x + threadIdx.x;
    if (idx < CZ * CC * CC) {
        const int z = idx >> 10;       // /1024
        const int k = idx & 1023;
        g_woT[k * CZ + z] = wo[idx];
    }
}

// ---------------------------------------------------------------------------
// K3: fused outer-product GEMM + output projection.
// Grid (64,64): CTA owns i in [i0,i0+4), j in [j0,j0+4). 256 threads.
// ---------------------------------------------------------------------------
__global__ __launch_bounds__(256, 1)
void opm_fused_kernel(const float* __restrict__ bo, float* __restrict__ out) {
    extern __shared__ float smem[];
    float* As = smem;            // [128 k][128 m]
    float* Bs = smem + 16384;    // [128 k][128 n]

    const int tid = threadIdx.x;
    const int tx = tid & 15, ty = tid >> 4;
    const int i0 = blockIdx.x * 4, j0 = blockIdx.y * 4;

    // Load full-K tiles (coalesced: m-contiguous rows of 128 floats).
    for (int idx = tid; idx < 16384; idx += 256) {
        const int k = idx >> 7, mm = idx & 127;
        As[idx] = g_a[(size_t)k * MDIM + i0 * CC + mm];
        Bs[idx] = g_b[(size_t)k * MDIM + j0 * CC + mm];
    }
    __syncthreads();

    // Phase 1: o[m][n] = sum_k As[k][m]*Bs[k][n], 8x8 per thread.
    float acc[8][8];
    #pragma unroll
    for (int r = 0; r < 8; r++)
        #pragma unroll
        for (int c = 0; c < 8; c++) acc[r][c] = 0.f;

    #pragma unroll 4
    for (int k = 0; k < 128; k++) {
        float af[8], bf[8];
        *(float4*)&af[0] = *(const float4*)&As[k * 128 + ty * 8];
        *(float4*)&af[4] = *(const float4*)&As[k * 128 + ty * 8 + 4];
        *(float4*)&bf[0] = *(const float4*)&Bs[k * 128 + tx * 8];
        *(float4*)&bf[4] = *(const float4*)&Bs[k * 128 + tx * 8 + 4];
        #pragma unroll
        for (int r = 0; r < 8; r++)
            #pragma unroll
            for (int c = 0; c < 8; c++)
                acc[r][c] = fmaf(af[r], bf[c], acc[r][c]);
    }
    __syncthreads();   // everyone done reading As/Bs; safe to overwrite

    // Stage o: Os[p][c*?+d], p = i_l*4 + j_l, padded strides.
    float* Os = smem;  // 16*1156*4 = 73984 B, fits in the 128 KB region
    #pragma unroll
    for (int r = 0; r < 8; r++) {
        const int mm = ty * 8 + r;
        const int i_l = mm >> 5, cpos = mm & 31;
        const int n0 = tx * 8;
        const int p = i_l * 4 + (n0 >> 5);            // constant over the 8 n's
        const int base = p * OS_PSTRIDE + cpos * OS_CSTRIDE + (n0 & 31);
        *(float4*)&Os[base]     = *(float4*)&acc[r][0];
        *(float4*)&Os[base + 4] = *(float4*)&acc[r][4];
    }
    __syncthreads();

    // Phase 2: Z[p][z] = sum_k Os[p][k] * woT[k][z].
    // Thread = (z, h): z = tid&127, handles 8 pairs p = h*8..h*8+7.
    // Os reads are warp-uniform broadcasts (conflict-free); woT reads coalesced.
    const int z = tid & 127, h = tid >> 7;
    float zacc[8];
    #pragma unroll
    for (int pp = 0; pp < 8; pp++) zacc[pp] = 0.f;

    #pragma unroll 2
    for (int k4 = 0; k4 < 1024; k4 += 4) {
        const float wv0 = g_woT[(k4 + 0) * CZ + z];
        const float wv1 = g_woT[(k4 + 1) * CZ + z];
        const float wv2 = g_woT[(k4 + 2) * CZ + z];
        const float wv3 = g_woT[(k4 + 3) * CZ + z];
        const int obase = (k4 >> 5) * OS_CSTRIDE + (k4 & 31);
        #pragma unroll
        for (int pp = 0; pp < 8; pp++) {
            const int p = h * 8 + pp;
            const float4 ov = *(const float4*)&Os[p * OS_PSTRIDE + obase];
            zacc[pp] = fmaf(ov.x, wv0, zacc[pp]);
            zacc[pp] = fmaf(ov.y, wv1, zacc[pp]);
            zacc[pp] = fmaf(ov.z, wv2, zacc[pp]);
            zacc[pp] = fmaf(ov.w, wv3, zacc[pp]);
        }
    }

    const float bias = bo[z];
    #pragma unroll
    for (int pp = 0; pp < 8; pp++) {
        const int p = h * 8 + pp;
        const int i_l = p >> 2, j_l = p & 3;
        out[(((size_t)(i0 + i_l)) * R_DIM + (j0 + j_l)) * CZ + z] =
            (zacc[pp] + bias) * (1.0f / S_DIM);
    }
}

// ---------------------------------------------------------------------------
extern "C" void kernel_launch(void* const* d_in, const int* in_sizes, int n_in,
                              void* d_out, int out_size) {
    const float* m    = (const float*)d_in[0];
    const float* ln_w = (const float*)d_in[1];
    const float* ln_b = (const float*)d_in[2];
    const float* w1   = (const float*)d_in[3];
    const float* b1   = (const float*)d_in[4];
    const float* w2   = (const float*)d_in[5];
    const float* b2   = (const float*)d_in[6];
    const float* wo   = (const float*)d_in[7];
    const float* bo   = (const float*)d_in[8];
    float* out = (float*)d_out;

    // Idempotent, capture-safe (no stream ops, no allocation).
    cudaFuncSetAttribute(opm_fused_kernel,
                         cudaFuncAttributeMaxDynamicSharedMemorySize, SMEM_BYTES);

    ln_proj_kernel<<<dim3(R_DIM, S_DIM), CM>>>(m, ln_w, ln_b, w1, b1, w2, b2);
    transpose_wo_kernel<<<(CZ * CC * CC + 255) / 256, 256>>>(wo);
    opm_fused_kernel<<<dim3(R_DIM / 4, R_DIM / 4), 256, SMEM_BYTES>>>(bo, out);
}

// round 5
// speedup vs baseline: 3.0305x; 3.0305x over previous
#include <cuda_runtime.h>
#include <cstdint>

// OuterProductMean — mma.sync tf32 (compute_103-safe), fully fused epilogue.
//
//  wo32       : g_wo32 = tf32(rna)-rounded copy of wo[z][k]        (prologue)
//  ln_proj    : LayerNorm + dual projection -> g_a[s][i*32+c], g_b[s][j*32+d]
//  fused      : per CTA (i-block 4, j-block 8):
//     phase1: o[128 (i,c)][256 (j,d)] = sum_s a*b       (mma tf32, K=128)
//     stage o -> SMEM Os (skew-swizzled), then
//     phase2: Z[32 pairs][128 z] = Os * wo^T (K=1024, cp.async double-buffered)

#define S_DIM 128
#define R_DIM 256
#define CM    256
#define CC    32
#define CZ    128
#define MDIM  (R_DIM * CC)          // 8192

__device__ float g_a[(size_t)S_DIM * MDIM];     // 4 MB  [s][m]
__device__ float g_b[(size_t)S_DIM * MDIM];     // 4 MB  [s][n]
__device__ float g_wo32[(size_t)CZ * CC * CC];  // 512 KB [z][k2]

// ---------------------------------------------------------------- helpers
__device__ __forceinline__ uint32_t su32(const void* p) {
    uint32_t a;
    asm("{ .reg .u64 t; cvta.to.shared.u64 t, %1; cvt.u32.u64 %0, t; }"
        : "=r"(a) : "l"(p));
    return a;
}
__device__ __forceinline__ uint32_t tf32r(float f) {
    uint32_t r;
    asm("cvt.rna.tf32.f32 %0, %1;" : "=r"(r) : "f"(f));
    return r;
}
__device__ __forceinline__ float tf32f(float f) { return __uint_as_float(tf32r(f)); }

__device__ __forceinline__ void cp16(void* dst_smem, const void* src) {
    asm volatile("cp.async.cg.shared.global [%0], [%1], 16;"
                 :: "r"(su32(dst_smem)), "l"(src));
}
__device__ __forceinline__ void cp_commit() {
    asm volatile("cp.async.commit_group;" ::: "memory");
}
template <int N>
__device__ __forceinline__ void cp_wait() {
    asm volatile("cp.async.wait_group %0;" :: "n"(N) : "memory");
}

// D(16x8) += A(16x8 row) * B(8x8 col), tf32
__device__ __forceinline__ void mma8(float* d, const uint32_t* a, uint32_t b0, uint32_t b1) {
    asm volatile(
        "mma.sync.aligned.m16n8k8.row.col.f32.tf32.tf32.f32 "
        "{%0,%1,%2,%3}, {%4,%5,%6,%7}, {%8,%9}, {%0,%1,%2,%3};"
        : "+f"(d[0]), "+f"(d[1]), "+f"(d[2]), "+f"(d[3])
        : "r"(a[0]), "r"(a[1]), "r"(a[2]), "r"(a[3]), "r"(b0), "r"(b1));
}

// ---------------------------------------------------------------- wo prologue
__global__ void wo32_kernel(const float* __restrict__ wo) {
    const int idx = blockIdx.x * blockDim.x + threadIdx.x;
    if (idx < CZ * CC * CC) g_wo32[idx] = tf32f(wo[idx]);
}

// ---------------------------------------------------------------- ln + proj
#define LN_STRIDE 264
#define LN_SMEM ((64 + 32) * LN_STRIDE * 4)

__global__ __launch_bounds__(256, 1)
void ln_proj(const float* __restrict__ m,
             const float* __restrict__ ln_w, const float* __restrict__ ln_b,
             const float* __restrict__ w1, const float* __restrict__ b1,
             const float* __restrict__ w2, const float* __restrict__ b2) {
    extern __shared__ __align__(16) float sm_[];
    float* ws = sm_;                     // [64][264]: w1 rows 0..31, w2 rows 32..63
    float* xs = sm_ + 64 * LN_STRIDE;    // [32][264] normalized rows

    const int s = blockIdx.x;
    const int tid = threadIdx.x, w = tid >> 5, lane = tid & 31;

    for (int idx = tid; idx < 64 * 64; idx += 256) {
        const int row = idx >> 6, k4 = idx & 63;
        const float* src = (row < 32) ? (w1 + (size_t)row * CM)
                                      : (w2 + (size_t)(row - 32) * CM);
        *(float4*)(ws + row * LN_STRIDE + k4 * 4) = *(const float4*)(src + k4 * 4);
    }

    const float4 lw0 = ((const float4*)ln_w)[lane], lw1 = ((const float4*)ln_w)[lane + 32];
    const float4 lb0 = ((const float4*)ln_b)[lane], lb1 = ((const float4*)ln_b)[lane + 32];

    const int o0 = (tid >> 3) * 2, r0 = tid & 7;
    const float bias0 = (o0 < 32) ? b1[o0] : b2[o0 - 32];
    const float bias1 = (o0 < 32) ? b1[o0 + 1] : b2[o0 + 1 - 32];

    for (int b0r = 0; b0r < R_DIM; b0r += 32) {
        __syncthreads();   // ws loaded / previous GEMM done reading xs
        #pragma unroll
        for (int p = 0; p < 4; p++) {
            const int r = p * 8 + w;
            const float* rowp = m + ((size_t)s * R_DIM + (b0r + r)) * CM;
            const float4 v0 = ((const float4*)rowp)[lane];
            const float4 v1 = ((const float4*)rowp)[lane + 32];
            float sum = v0.x + v0.y + v0.z + v0.w + v1.x + v1.y + v1.z + v1.w;
            #pragma unroll
            for (int o = 16; o; o >>= 1) sum += __shfl_xor_sync(~0u, sum, o);
            const float mu = sum * (1.0f / CM);
            const float d0 = v0.x - mu, d1 = v0.y - mu, d2 = v0.z - mu, d3 = v0.w - mu;
            const float d4 = v1.x - mu, d5 = v1.y - mu, d6 = v1.z - mu, d7 = v1.w - mu;
            float vs = d0*d0 + d1*d1 + d2*d2 + d3*d3 + d4*d4 + d5*d5 + d6*d6 + d7*d7;
            #pragma unroll
            for (int o = 16; o; o >>= 1) vs += __shfl_xor_sync(~0u, vs, o);
            const float rstd = rsqrtf(vs * (1.0f / CM) + 1e-5f);
            float4 y0, y1;
            y0.x = d0 * rstd * lw0.x + lb0.x;  y0.y = d1 * rstd * lw0.y + lb0.y;
            y0.z = d2 * rstd * lw0.z + lb0.z;  y0.w = d3 * rstd * lw0.w + lb0.w;
            y1.x = d4 * rstd * lw1.x + lb1.x;  y1.y = d5 * rstd * lw1.y + lb1.y;
            y1.z = d6 * rstd * lw1.z + lb1.z;  y1.w = d7 * rstd * lw1.w + lb1.w;
            *(float4*)(xs + r * LN_STRIDE + 4 * lane)       = y0;
            *(float4*)(xs + r * LN_STRIDE + 128 + 4 * lane) = y1;
        }
        __syncthreads();

        // thread -> outputs {o0, o0+1}, rows {r0, r0+8, r0+16, r0+24}
        float acc0[4] = {0.f, 0.f, 0.f, 0.f}, acc1[4] = {0.f, 0.f, 0.f, 0.f};
        const float* wr0 = ws + o0 * LN_STRIDE;
        const float* wr1 = wr0 + LN_STRIDE;
        #pragma unroll 8
        for (int k4 = 0; k4 < 64; k4++) {
            const float4 wa = *(const float4*)(wr0 + k4 * 4);
            const float4 wb = *(const float4*)(wr1 + k4 * 4);
            #pragma unroll
            for (int u = 0; u < 4; u++) {
                const float4 x = *(const float4*)(xs + (r0 + 8 * u) * LN_STRIDE + k4 * 4);
                acc0[u] = fmaf(wa.x, x.x, acc0[u]); acc0[u] = fmaf(wa.y, x.y, acc0[u]);
                acc0[u] = fmaf(wa.z, x.z, acc0[u]); acc0[u] = fmaf(wa.w, x.w, acc0[u]);
                acc1[u] = fmaf(wb.x, x.x, acc1[u]); acc1[u] = fmaf(wb.y, x.y, acc1[u]);
                acc1[u] = fmaf(wb.z, x.z, acc1[u]); acc1[u] = fmaf(wb.w, x.w, acc1[u]);
            }
        }
        #pragma unroll
        for (int u = 0; u < 4; u++) {
            const int i_abs = b0r + r0 + 8 * u;
            float2 v;
            v.x = acc0[u] + bias0;
            v.y = acc1[u] + bias1;
            if (o0 < 32)
                *(float2*)&g_a[(size_t)s * MDIM + i_abs * CC + o0] = v;
            else
                *(float2*)&g_b[(size_t)s * MDIM + i_abs * CC + (o0 - 32)] = v;
        }
    }
}

// ---------------------------------------------------------------- fused
// SMEM (floats):
//   phase1: sA[k=128][136]  (17408), sB[k=128][264] (33792)  -> 51200 fl (204800 B)
//   phase2: Os[k2=1024][36] (36864), wo 2x[128][68] (17408)  -> 54272 fl (217088 B)
#define SA_STRIDE 136
#define SB_STRIDE 264
#define SB_OFF    (128 * SA_STRIDE)
#define OS_STRIDE 36
#define WO_OFF    (1024 * OS_STRIDE)     // 36864 floats
#define WO_BUF    (128 * 68)             // 8704 floats
#define FUSED_SMEM ((WO_OFF + 2 * WO_BUF) * 4)   // 217088 B

__device__ __forceinline__ void issue_wo(float* buf, int cc, int tid) {
    #pragma unroll
    for (int t = 0; t < 4; t++) {
        const int idx = tid + t * 512;
        const int z = idx >> 4, q = idx & 15;
        cp16(buf + z * 68 + 4 * q, g_wo32 + (size_t)z * 1024 + cc * 64 + 4 * q);
    }
}

__global__ __launch_bounds__(512, 1)
void fused_kernel(const float* __restrict__ bo, float* __restrict__ out) {
    extern __shared__ __align__(16) float sm[];
    const int tid = threadIdx.x, w = tid >> 5, lane = tid & 31;
    const int g = lane >> 2, tg = lane & 3;
    const int i0 = blockIdx.x * 4, j0 = blockIdx.y * 8;
    const int m0 = i0 * CC, n0 = j0 * CC;

    // ---- load A tile [k][m] and B tile [k][n] (tf32-rounded) ----
    for (int idx = tid; idx < 128 * 32; idx += 512) {
        const int k = idx >> 5, q = idx & 31;
        const float4 v = *(const float4*)&g_a[(size_t)k * MDIM + m0 + 4 * q];
        float4 r; r.x = tf32f(v.x); r.y = tf32f(v.y); r.z = tf32f(v.z); r.w = tf32f(v.w);
        *(float4*)&sm[k * SA_STRIDE + 4 * q] = r;
    }
    for (int idx = tid; idx < 128 * 64; idx += 512) {
        const int k = idx >> 6, q = idx & 63;
        const float4 v = *(const float4*)&g_b[(size_t)k * MDIM + n0 + 4 * q];
        float4 r; r.x = tf32f(v.x); r.y = tf32f(v.y); r.z = tf32f(v.z); r.w = tf32f(v.w);
        *(float4*)&sm[SB_OFF + k * SB_STRIDE + 4 * q] = r;
    }
    __syncthreads();

    // ---- phase 1: o[128][256] = A * B^T over k=128 ----
    const int mr = w >> 2, nc = w & 3;          // warp tile: rows 32*mr, cols 64*nc
    const int mA = 32 * mr + g;
    const int nB = 64 * nc + g;

    float acc[2][8][4];
    #pragma unroll
    for (int mt = 0; mt < 2; mt++)
        #pragma unroll
        for (int nt = 0; nt < 8; nt++)
            #pragma unroll
            for (int q = 0; q < 4; q++) acc[mt][nt][q] = 0.f;

    #pragma unroll
    for (int ks = 0; ks < 16; ks++) {
        const int k0 = ks * 8;
        uint32_t a[2][4];
        #pragma unroll
        for (int mt = 0; mt < 2; mt++) {
            const int mb = mA + 16 * mt;
            a[mt][0] = __float_as_uint(sm[(k0 + tg)     * SA_STRIDE + mb]);
            a[mt][1] = __float_as_uint(sm[(k0 + tg)     * SA_STRIDE + mb + 8]);
            a[mt][2] = __float_as_uint(sm[(k0 + tg + 4) * SA_STRIDE + mb]);
            a[mt][3] = __float_as_uint(sm[(k0 + tg + 4) * SA_STRIDE + mb + 8]);
        }
        #pragma unroll
        for (int nt = 0; nt < 8; nt++) {
            const uint32_t b0 = __float_as_uint(sm[SB_OFF + (k0 + tg)     * SB_STRIDE + nB + 8 * nt]);
            const uint32_t b1 = __float_as_uint(sm[SB_OFF + (k0 + tg + 4) * SB_STRIDE + nB + 8 * nt]);
            mma8(acc[0][nt], a[0], b0, b1);
            mma8(acc[1][nt], a[1], b0, b1);
        }
    }
    __syncthreads();   // all warps done reading sA/sB

    // ---- stage o -> Os[k2][(p + c) & 31], k2 = c*32 + d (tf32-rounded) ----
    float* Os = sm;
    #pragma unroll
    for (int mt = 0; mt < 2; mt++) {
        #pragma unroll
        for (int nt = 0; nt < 8; nt++) {
            const int p  = mr * 8 + 2 * nc + (nt >> 2);
            const int dd = 8 * (nt & 3) + 2 * tg;
            const int c0 = 16 * mt + g;
            #pragma unroll
            for (int rr = 0; rr < 2; rr++) {
                const int c = c0 + 8 * rr;
                const int sl = (p + c) & 31;
                Os[(c * 32 + dd)     * OS_STRIDE + sl] = tf32f(acc[mt][nt][2 * rr + 0]);
                Os[(c * 32 + dd + 1) * OS_STRIDE + sl] = tf32f(acc[mt][nt][2 * rr + 1]);
            }
        }
    }

    float* wob0 = sm + WO_OFF;
    float* wob1 = sm + WO_OFF + WO_BUF;
    issue_wo(wob0, 0, tid); cp_commit();
    issue_wo(wob1, 1, tid); cp_commit();

    // ---- phase 2: Z[32][128] = Os * wo^T over k2=1024 ----
    const int mt2 = w & 1, ng = w >> 1;          // warp: 16 pairs x 16 z
    float zacc[2][4];
    #pragma unroll
    for (int t = 0; t < 2; t++)
        #pragma unroll
        for (int q = 0; q < 4; q++) zacc[t][q] = 0.f;

    const int p_ = 16 * mt2 + g;

    for (int cc = 0; cc < 16; cc++) {
        cp_wait<1>();
        __syncthreads();                          // chunk cc ready; Os visible (cc=0)
        const float* W = (cc & 1) ? wob1 : wob0;
        #pragma unroll
        for (int ks = 0; ks < 8; ks++) {
            const int k2 = cc * 64 + ks * 8;
            const int c_hi = k2 >> 5;
            uint32_t a[4];
            a[0] = __float_as_uint(Os[(k2 + tg)     * OS_STRIDE + ((p_     + c_hi) & 31)]);
            a[1] = __float_as_uint(Os[(k2 + tg)     * OS_STRIDE + ((p_ + 8 + c_hi) & 31)]);
            a[2] = __float_as_uint(Os[(k2 + tg + 4) * OS_STRIDE + ((p_     + c_hi) & 31)]);
            a[3] = __float_as_uint(Os[(k2 + tg + 4) * OS_STRIDE + ((p_ + 8 + c_hi) & 31)]);
            const int kc = ks * 8;
            #pragma unroll
            for (int t = 0; t < 2; t++) {
                const int zz = 16 * ng + 8 * t + g;
                const uint32_t b0 = __float_as_uint(W[zz * 68 + kc + tg]);
                const uint32_t b1 = __float_as_uint(W[zz * 68 + kc + tg + 4]);
                mma8(zacc[t], a, b0, b1);
            }
        }
        __syncthreads();                          // all warps done with this buffer
        if (cc + 2 < 16) issue_wo((cc & 1) ? wob1 : wob0, cc + 2, tid);
        cp_commit();                              // unconditional: keeps wait<1> math valid
    }

    // ---- epilogue ----
    #pragma unroll
    for (int t = 0; t < 2; t++) {
        const int zz = 16 * ng + 8 * t + 2 * tg;
        const float2 bo2 = *(const float2*)&bo[zz];
        #pragma unroll
        for (int rr = 0; rr < 2; rr++) {
            const int p = p_ + 8 * rr;
            const int i = i0 + (p >> 3), j = j0 + (p & 7);
            float2 v;
            v.x = (zacc[t][2 * rr + 0] + bo2.x) * (1.0f / S_DIM);
            v.y = (zacc[t][2 * rr + 1] + bo2.y) * (1.0f / S_DIM);
            *(float2*)&out[((size_t)i * R_DIM + j) * CZ + zz] = v;
        }
    }
}

// ---------------------------------------------------------------- launch
extern "C" void kernel_launch(void* const* d_in, const int* in_sizes, int n_in,
                              void* d_out, int out_size) {
    const float* m    = (const float*)d_in[0];
    const float* ln_w = (const float*)d_in[1];
    const float* ln_b = (const float*)d_in[2];
    const float* w1   = (const float*)d_in[3];
    const float* b1   = (const float*)d_in[4];
    const float* w2   = (const float*)d_in[5];
    const float* b2   = (const float*)d_in[6];
    const float* wo   = (const float*)d_in[7];
    const float* bo   = (const float*)d_in[8];
    float* out = (float*)d_out;

    cudaFuncSetAttribute(ln_proj, cudaFuncAttributeMaxDynamicSharedMemorySize, LN_SMEM);
    cudaFuncSetAttribute(fused_kernel, cudaFuncAttributeMaxDynamicSharedMemorySize, FUSED_SMEM);

    wo32_kernel<<<(CZ * CC * CC + 255) / 256, 256>>>(wo);
    ln_proj<<<S_DIM, 256, LN_SMEM>>>(m, ln_w, ln_b, w1, b1, w2, b2);
    fused_kernel<<<dim3(R_DIM / 4, R_DIM / 8), 512, FUSED_SMEM>>>(bo, out);
}

// round 6
// speedup vs baseline: 3.4060x; 1.1239x over previous
#include <cuda_runtime.h>
#include <cstdint>

// OuterProductMean — mma.sync tf32 (compute_103-safe), fully fused epilogue.
//
//  ln_wo      : blocks 0..127: LayerNorm + dual projection -> g_a[s][.], g_b[s][.]
//               blocks 128..159: g_wo32 = tf32(rna)-rounded wo
//  fused      : per CTA (i-block 4, j-block 8):
//     phase1: o[128 (i,c)][256 (j,d)] = sum_s a*b       (mma tf32, K=128)
//     stage o -> SMEM Os (skew-swizzled), then
//     phase2: Z[32 pairs][128 z] = Os * wo^T (K=1024, cp.async double-buffered,
//             2-way within-chunk k-split + final cross-warp reduction)

#define S_DIM 128
#define R_DIM 256
#define CM    256
#define CC    32
#define CZ    128
#define MDIM  (R_DIM * CC)          // 8192

__device__ float g_a[(size_t)S_DIM * MDIM];     // 4 MB  [s][m]
__device__ float g_b[(size_t)S_DIM * MDIM];     // 4 MB  [s][n]
__device__ float g_wo32[(size_t)CZ * CC * CC];  // 512 KB [z][k2]

// ---------------------------------------------------------------- helpers
__device__ __forceinline__ uint32_t su32(const void* p) {
    uint32_t a;
    asm("{ .reg .u64 t; cvta.to.shared.u64 t, %1; cvt.u32.u64 %0, t; }"
        : "=r"(a) : "l"(p));
    return a;
}
__device__ __forceinline__ uint32_t tf32r(float f) {
    uint32_t r;
    asm("cvt.rna.tf32.f32 %0, %1;" : "=r"(r) : "f"(f));
    return r;
}
__device__ __forceinline__ float tf32f(float f) { return __uint_as_float(tf32r(f)); }

__device__ __forceinline__ void cp16(void* dst_smem, const void* src) {
    asm volatile("cp.async.cg.shared.global [%0], [%1], 16;"
                 :: "r"(su32(dst_smem)), "l"(src));
}
__device__ __forceinline__ void cp_commit() {
    asm volatile("cp.async.commit_group;" ::: "memory");
}
template <int N>
__device__ __forceinline__ void cp_wait() {
    asm volatile("cp.async.wait_group %0;" :: "n"(N) : "memory");
}

// D(16x8) += A(16x8 row) * B(8x8 col), tf32
__device__ __forceinline__ void mma8(float* d, const uint32_t* a, uint32_t b0, uint32_t b1) {
    asm volatile(
        "mma.sync.aligned.m16n8k8.row.col.f32.tf32.tf32.f32 "
        "{%0,%1,%2,%3}, {%4,%5,%6,%7}, {%8,%9}, {%0,%1,%2,%3};"
        : "+f"(d[0]), "+f"(d[1]), "+f"(d[2]), "+f"(d[3])
        : "r"(a[0]), "r"(a[1]), "r"(a[2]), "r"(a[3]), "r"(b0), "r"(b1));
}

// ---------------------------------------------------------------- ln + proj (+ wo convert)
#define LN_STRIDE 264
#define LN_SMEM ((64 + 32) * LN_STRIDE * 4)

__global__ __launch_bounds__(256, 1)
void ln_wo_kernel(const float* __restrict__ m,
                  const float* __restrict__ ln_w, const float* __restrict__ ln_b,
                  const float* __restrict__ w1, const float* __restrict__ b1,
                  const float* __restrict__ w2, const float* __restrict__ b2,
                  const float* __restrict__ wo) {
    // blocks 128..159: tf32-round wo (32 blocks * 256 thr * 16 elems = 131072)
    if (blockIdx.x >= S_DIM) {
        const int base = ((blockIdx.x - S_DIM) * 256 + threadIdx.x) * 16;
        #pragma unroll
        for (int t = 0; t < 4; t++) {
            const float4 v = *(const float4*)&wo[base + 4 * t];
            float4 r; r.x = tf32f(v.x); r.y = tf32f(v.y); r.z = tf32f(v.z); r.w = tf32f(v.w);
            *(float4*)&g_wo32[base + 4 * t] = r;
        }
        return;
    }

    extern __shared__ __align__(16) float sm_[];
    float* ws = sm_;                     // [64][264]: w1 rows 0..31, w2 rows 32..63
    float* xs = sm_ + 64 * LN_STRIDE;    // [32][264] normalized rows

    const int s = blockIdx.x;
    const int tid = threadIdx.x, w = tid >> 5, lane = tid & 31;

    for (int idx = tid; idx < 64 * 64; idx += 256) {
        const int row = idx >> 6, k4 = idx & 63;
        const float* src = (row < 32) ? (w1 + (size_t)row * CM)
                                      : (w2 + (size_t)(row - 32) * CM);
        *(float4*)(ws + row * LN_STRIDE + k4 * 4) = *(const float4*)(src + k4 * 4);
    }

    const float4 lw0 = ((const float4*)ln_w)[lane], lw1 = ((const float4*)ln_w)[lane + 32];
    const float4 lb0 = ((const float4*)ln_b)[lane], lb1 = ((const float4*)ln_b)[lane + 32];

    const int o0 = (tid >> 3) * 2, r0 = tid & 7;
    const float bias0 = (o0 < 32) ? b1[o0] : b2[o0 - 32];
    const float bias1 = (o0 < 32) ? b1[o0 + 1] : b2[o0 + 1 - 32];

    for (int b0r = 0; b0r < R_DIM; b0r += 32) {
        __syncthreads();   // ws loaded / previous GEMM done reading xs
        #pragma unroll
        for (int p = 0; p < 4; p++) {
            const int r = p * 8 + w;
            const float* rowp = m + ((size_t)s * R_DIM + (b0r + r)) * CM;
            const float4 v0 = ((const float4*)rowp)[lane];
            const float4 v1 = ((const float4*)rowp)[lane + 32];
            float sum = v0.x + v0.y + v0.z + v0.w + v1.x + v1.y + v1.z + v1.w;
            #pragma unroll
            for (int o = 16; o; o >>= 1) sum += __shfl_xor_sync(~0u, sum, o);
            const float mu = sum * (1.0f / CM);
            const float d0 = v0.x - mu, d1 = v0.y - mu, d2 = v0.z - mu, d3 = v0.w - mu;
            const float d4 = v1.x - mu, d5 = v1.y - mu, d6 = v1.z - mu, d7 = v1.w - mu;
            float vs = d0*d0 + d1*d1 + d2*d2 + d3*d3 + d4*d4 + d5*d5 + d6*d6 + d7*d7;
            #pragma unroll
            for (int o = 16; o; o >>= 1) vs += __shfl_xor_sync(~0u, vs, o);
            const float rstd = rsqrtf(vs * (1.0f / CM) + 1e-5f);
            float4 y0, y1;
            y0.x = d0 * rstd * lw0.x + lb0.x;  y0.y = d1 * rstd * lw0.y + lb0.y;
            y0.z = d2 * rstd * lw0.z + lb0.z;  y0.w = d3 * rstd * lw0.w + lb0.w;
            y1.x = d4 * rstd * lw1.x + lb1.x;  y1.y = d5 * rstd * lw1.y + lb1.y;
            y1.z = d6 * rstd * lw1.z + lb1.z;  y1.w = d7 * rstd * lw1.w + lb1.w;
            *(float4*)(xs + r * LN_STRIDE + 4 * lane)       = y0;
            *(float4*)(xs + r * LN_STRIDE + 128 + 4 * lane) = y1;
        }
        __syncthreads();

        // thread -> outputs {o0, o0+1}, rows {r0, r0+8, r0+16, r0+24}
        float acc0[4] = {0.f, 0.f, 0.f, 0.f}, acc1[4] = {0.f, 0.f, 0.f, 0.f};
        const float* wr0 = ws + o0 * LN_STRIDE;
        const float* wr1 = wr0 + LN_STRIDE;
        #pragma unroll 8
        for (int k4 = 0; k4 < 64; k4++) {
            const float4 wa = *(const float4*)(wr0 + k4 * 4);
            const float4 wb = *(const float4*)(wr1 + k4 * 4);
            #pragma unroll
            for (int u = 0; u < 4; u++) {
                const float4 x = *(const float4*)(xs + (r0 + 8 * u) * LN_STRIDE + k4 * 4);
                acc0[u] = fmaf(wa.x, x.x, acc0[u]); acc0[u] = fmaf(wa.y, x.y, acc0[u]);
                acc0[u] = fmaf(wa.z, x.z, acc0[u]); acc0[u] = fmaf(wa.w, x.w, acc0[u]);
                acc1[u] = fmaf(wb.x, x.x, acc1[u]); acc1[u] = fmaf(wb.y, x.y, acc1[u]);
                acc1[u] = fmaf(wb.z, x.z, acc1[u]); acc1[u] = fmaf(wb.w, x.w, acc1[u]);
            }
        }
        #pragma unroll
        for (int u = 0; u < 4; u++) {
            const int i_abs = b0r + r0 + 8 * u;
            float2 v;
            v.x = acc0[u] + bias0;
            v.y = acc1[u] + bias1;
            if (o0 < 32)
                *(float2*)&g_a[(size_t)s * MDIM + i_abs * CC + o0] = v;
            else
                *(float2*)&g_b[(size_t)s * MDIM + i_abs * CC + (o0 - 32)] = v;
        }
    }
}

// ---------------------------------------------------------------- fused
// SMEM (floats):
//   phase1: sA[k=128][136]  (17408), sB[k=128][264] (33792)  -> 51200 fl (204800 B)
//   phase2: Os[k2=1024][36] (36864), wo 2x[128][68] (17408)  -> 54272 fl (217088 B)
//   reduction scratch (8*32*20 = 5120 fl) reuses wo-buffer region at WO_OFF.
#define SA_STRIDE 136
#define SB_STRIDE 264
#define SB_OFF    (128 * SA_STRIDE)
#define OS_STRIDE 36
#define WO_OFF    (1024 * OS_STRIDE)     // 36864 floats
#define WO_BUF    (128 * 68)             // 8704 floats
#define FUSED_SMEM ((WO_OFF + 2 * WO_BUF) * 4)   // 217088 B

__device__ __forceinline__ void issue_wo(float* buf, int cc, int tid) {
    #pragma unroll
    for (int t = 0; t < 4; t++) {
        const int idx = tid + t * 512;
        const int z = idx >> 4, q = idx & 15;
        cp16(buf + z * 68 + 4 * q, g_wo32 + (size_t)z * 1024 + cc * 64 + 4 * q);
    }
}

__global__ __launch_bounds__(512, 1)
void fused_kernel(const float* __restrict__ bo, float* __restrict__ out) {
    extern __shared__ __align__(16) float sm[];
    const int tid = threadIdx.x, w = tid >> 5, lane = tid & 31;
    const int g = lane >> 2, tg = lane & 3;
    const int i0 = blockIdx.x * 4, j0 = blockIdx.y * 8;
    const int m0 = i0 * CC, n0 = j0 * CC;

    // ---- load A tile [k][m] and B tile [k][n] (tf32-rounded) ----
    for (int idx = tid; idx < 128 * 32; idx += 512) {
        const int k = idx >> 5, q = idx & 31;
        const float4 v = *(const float4*)&g_a[(size_t)k * MDIM + m0 + 4 * q];
        float4 r; r.x = tf32f(v.x); r.y = tf32f(v.y); r.z = tf32f(v.z); r.w = tf32f(v.w);
        *(float4*)&sm[k * SA_STRIDE + 4 * q] = r;
    }
    for (int idx = tid; idx < 128 * 64; idx += 512) {
        const int k = idx >> 6, q = idx & 63;
        const float4 v = *(const float4*)&g_b[(size_t)k * MDIM + n0 + 4 * q];
        float4 r; r.x = tf32f(v.x); r.y = tf32f(v.y); r.z = tf32f(v.z); r.w = tf32f(v.w);
        *(float4*)&sm[SB_OFF + k * SB_STRIDE + 4 * q] = r;
    }
    __syncthreads();

    // ---- phase 1: o[128][256] = A * B^T over k=128 ----
    const int mr = w >> 2, nc = w & 3;          // warp tile: rows 32*mr, cols 64*nc
    const int mA = 32 * mr + g;
    const int nB = 64 * nc + g;

    float acc[2][8][4];
    #pragma unroll
    for (int mt = 0; mt < 2; mt++)
        #pragma unroll
        for (int nt = 0; nt < 8; nt++)
            #pragma unroll
            for (int q = 0; q < 4; q++) acc[mt][nt][q] = 0.f;

    #pragma unroll
    for (int ks = 0; ks < 16; ks++) {
        const int k0 = ks * 8;
        uint32_t a[2][4];
        #pragma unroll
        for (int mt = 0; mt < 2; mt++) {
            const int mb = mA + 16 * mt;
            a[mt][0] = __float_as_uint(sm[(k0 + tg)     * SA_STRIDE + mb]);
            a[mt][1] = __float_as_uint(sm[(k0 + tg)     * SA_STRIDE + mb + 8]);
            a[mt][2] = __float_as_uint(sm[(k0 + tg + 4) * SA_STRIDE + mb]);
            a[mt][3] = __float_as_uint(sm[(k0 + tg + 4) * SA_STRIDE + mb + 8]);
        }
        #pragma unroll
        for (int nt = 0; nt < 8; nt++) {
            const uint32_t b0 = __float_as_uint(sm[SB_OFF + (k0 + tg)     * SB_STRIDE + nB + 8 * nt]);
            const uint32_t b1 = __float_as_uint(sm[SB_OFF + (k0 + tg + 4) * SB_STRIDE + nB + 8 * nt]);
            mma8(acc[0][nt], a[0], b0, b1);
            mma8(acc[1][nt], a[1], b0, b1);
        }
    }
    __syncthreads();   // all warps done reading sA/sB

    // ---- issue wo chunks 0/1 now (regions beyond sA, disjoint from Os) ----
    float* wob0 = sm + WO_OFF;
    float* wob1 = sm + WO_OFF + WO_BUF;
    issue_wo(wob0, 0, tid); cp_commit();
    issue_wo(wob1, 1, tid); cp_commit();

    // ---- stage o -> Os[k2][(p + c) & 31], k2 = c*32 + d (tf32-rounded) ----
    float* Os = sm;
    #pragma unroll
    for (int mt = 0; mt < 2; mt++) {
        #pragma unroll
        for (int nt = 0; nt < 8; nt++) {
            const int p  = mr * 8 + 2 * nc + (nt >> 2);
            const int dd = 8 * (nt & 3) + 2 * tg;
            const int c0 = 16 * mt + g;
            #pragma unroll
            for (int rr = 0; rr < 2; rr++) {
                const int c = c0 + 8 * rr;
                const int sl = (p + c) & 31;
                Os[(c * 32 + dd)     * OS_STRIDE + sl] = tf32f(acc[mt][nt][2 * rr + 0]);
                Os[(c * 32 + dd + 1) * OS_STRIDE + sl] = tf32f(acc[mt][nt][2 * rr + 1]);
            }
        }
    }

    // ---- phase 2: Z[32][128] = Os * wo^T over k2=1024 ----
    // 2-way within-chunk k-split: warp w -> kg = w>>3 (k-half of each chunk),
    // sub = w&7: mh = sub&1 (pair 16-half), zg = sub>>1 (z 32-group).
    const int kg = w >> 3, sub = w & 7;
    const int mh = sub & 1, zg = sub >> 1;
    const int p_ = 16 * mh + g;

    float zacc[4][4];
    #pragma unroll
    for (int nt = 0; nt < 4; nt++)
        #pragma unroll
        for (int q = 0; q < 4; q++) zacc[nt][q] = 0.f;

    for (int cc = 0; cc < 16; cc++) {
        cp_wait<1>();
        __syncthreads();                          // chunk cc ready; Os visible (cc=0)
        const float* W = (cc & 1) ? wob1 : wob0;
        #pragma unroll
        for (int ks4 = 0; ks4 < 4; ks4++) {
            const int ks = kg * 4 + ks4;          // 0..7 within chunk
            const int k2 = cc * 64 + ks * 8;
            const int c_hi = k2 >> 5;
            uint32_t a[4];
            a[0] = __float_as_uint(Os[(k2 + tg)     * OS_STRIDE + ((p_     + c_hi) & 31)]);
            a[1] = __float_as_uint(Os[(k2 + tg)     * OS_STRIDE + ((p_ + 8 + c_hi) & 31)]);
            a[2] = __float_as_uint(Os[(k2 + tg + 4) * OS_STRIDE + ((p_     + c_hi) & 31)]);
            a[3] = __float_as_uint(Os[(k2 + tg + 4) * OS_STRIDE + ((p_ + 8 + c_hi) & 31)]);
            const int kc = ks * 8;
            #pragma unroll
            for (int nt = 0; nt < 4; nt++) {
                const int zz = 32 * zg + 8 * nt + g;
                const uint32_t b0 = __float_as_uint(W[zz * 68 + kc + tg]);
                const uint32_t b1 = __float_as_uint(W[zz * 68 + kc + tg + 4]);
                mma8(zacc[nt], a, b0, b1);
            }
        }
        __syncthreads();                          // all warps done with this buffer
        if (cc + 2 < 16) issue_wo((cc & 1) ? wob1 : wob0, cc + 2, tid);
        cp_commit();                              // unconditional: keeps wait<1> math valid
    }

    // ---- cross-k-half reduction: warps 8..15 -> scratch, warps 0..7 add ----
    float* scratch = sm + WO_OFF;                 // 8*32*20 floats, stride-20 padded
    if (w >= 8) {
        float* dst = scratch + ((w - 8) * 32 + lane) * 20;
        #pragma unroll
        for (int nt = 0; nt < 4; nt++)
            *(float4*)&dst[nt * 4] = *(float4*)&zacc[nt][0];
    }
    __syncthreads();
    if (w < 8) {
        const float* src = scratch + (w * 32 + lane) * 20;
        #pragma unroll
        for (int nt = 0; nt < 4; nt++) {
            const float4 v = *(const float4*)&src[nt * 4];
            zacc[nt][0] += v.x; zacc[nt][1] += v.y;
            zacc[nt][2] += v.z; zacc[nt][3] += v.w;
        }

        // ---- epilogue (warps 0..7 hold full-k sums) ----
        #pragma unroll
        for (int nt = 0; nt < 4; nt++) {
            const int zz = 32 * zg + 8 * nt + 2 * tg;
            const float2 bo2 = *(const float2*)&bo[zz];
            #pragma unroll
            for (int rr = 0; rr < 2; rr++) {
                const int p = p_ + 8 * rr;
                const int i = i0 + (p >> 3), j = j0 + (p & 7);
                float2 v;
                v.x = (zacc[nt][2 * rr + 0] + bo2.x) * (1.0f / S_DIM);
                v.y = (zacc[nt][2 * rr + 1] + bo2.y) * (1.0f / S_DIM);
                *(float2*)&out[((size_t)i * R_DIM + j) * CZ + zz] = v;
            }
        }
    }
}

// ---------------------------------------------------------------- launch
extern "C" void kernel_launch(void* const* d_in, const int* in_sizes, int n_in,
                              void* d_out, int out_size) {
    const float* m    = (const float*)d_in[0];
    const float* ln_w = (const float*)d_in[1];
    const float* ln_b = (const float*)d_in[2];
    const float* w1   = (const float*)d_in[3];
    const float* b1   = (const float*)d_in[4];
    const float* w2   = (const float*)d_in[5];
    const float* b2   = (const float*)d_in[6];
    const float* wo   = (const float*)d_in[7];
    const float* bo   = (const float*)d_in[8];
    float* out = (float*)d_out;

    cudaFuncSetAttribute(ln_wo_kernel, cudaFuncAttributeMaxDynamicSharedMemorySize, LN_SMEM);
    cudaFuncSetAttribute(fused_kernel, cudaFuncAttributeMaxDynamicSharedMemorySize, FUSED_SMEM);

    ln_wo_kernel<<<S_DIM + 32, 256, LN_SMEM>>>(m, ln_w, ln_b, w1, b1, w2, b2, wo);
    fused_kernel<<<dim3(R_DIM / 4, R_DIM / 8), 512, FUSED_SMEM>>>(bo, out);
}